// round 9
// baseline (speedup 1.0000x reference)
#include <cuda_runtime.h>
#include <cuda_bf16.h>
#include <cstdint>

#define NKV      8
#define GROUP    4
#define NHEADS   32
#define BATCH    512
#define HEAD_DIM 128
#define CACHE    2048
#define NEG_INF  (-10000.0f)
#define M_REF    40.0f
#define THREADS  256
#define BM       64
#define BN       64

// Q/K(P) tiles: 64 rows x 136 bf16 (272 B stride). V tile: 128 rows x 72 bf16 (144 B stride).
#define QK_STRIDE 272
#define V_STRIDE  144
#define QKBUF (64 * QK_STRIDE)     // 17408
#define VBUF  (128 * V_STRIDE)     // 18432

#define OFF_L    0                 // float lrow[64]
#define OFF_QHI  512
#define OFF_QLO  (OFF_QHI + QKBUF)
#define OFF_KHI  (OFF_QLO + QKBUF)   // reused as P_hi after QK
#define OFF_KLO  (OFF_KHI + QKBUF)   // reused as P_lo
#define OFF_VHI  (OFF_KLO + QKBUF)
#define OFF_VLO  (OFF_VHI + VBUF)
#define SMEM_TOTAL (OFF_VLO + VBUF)  // 512 + 4*17408 + 2*18432 = 107008 (x2 CTAs = 209KB/SM)

__device__ __forceinline__ uint32_t smem_u32(const void* p) {
    uint32_t a;
    asm("{ .reg .u64 t; cvta.to.shared.u64 t, %1; cvt.u32.u64 %0, t; }" : "=r"(a) : "l"(p));
    return a;
}

__device__ __forceinline__ uint32_t qkoff(int r, int c) { return (uint32_t)(r * QK_STRIDE + c * 2); }
__device__ __forceinline__ uint32_t voff (int r, int c) { return (uint32_t)(r * V_STRIDE  + c * 2); }

__device__ __forceinline__ void ldsm4(uint32_t* r, uint32_t addr) {
    asm volatile("ldmatrix.sync.aligned.m8n8.x4.shared.b16 {%0,%1,%2,%3}, [%4];"
                 : "=r"(r[0]), "=r"(r[1]), "=r"(r[2]), "=r"(r[3]) : "r"(addr));
}

__device__ __forceinline__ void mma16816(float* c, const uint32_t* a, uint32_t b0, uint32_t b1) {
    asm volatile("mma.sync.aligned.m16n8k16.row.col.f32.bf16.bf16.f32 "
                 "{%0,%1,%2,%3}, {%4,%5,%6,%7}, {%8,%9}, {%0,%1,%2,%3};"
                 : "+f"(c[0]), "+f"(c[1]), "+f"(c[2]), "+f"(c[3])
                 : "r"(a[0]), "r"(a[1]), "r"(a[2]), "r"(a[3]), "r"(b0), "r"(b1));
}

__device__ __forceinline__ uint32_t bpack(float a, float b) {
    __nv_bfloat162 t = __floats2bfloat162_rn(a, b);
    return *reinterpret_cast<uint32_t*>(&t);
}
__device__ __forceinline__ void split_pair(float a, float b, uint32_t& hi, uint32_t& lo) {
    float ah = __bfloat162float(__float2bfloat16(a));
    float bh = __bfloat162float(__float2bfloat16(b));
    hi = bpack(ah, bh);
    lo = bpack(a - ah, b - bh);
}

// MMA pass, warp tile = 16 rows x (NB*8) cols, K = KC*16.
// A: 16 rows at r0, stride QK_STRIDE. B: rows c0..c0+NB*8-1, stride bstride. acc[NB][4].
template<int KC, int NB>
__device__ __forceinline__ void gemm16(uint32_t Ab, uint32_t Bb, int bstride,
                                       int r0, int c0, int lane, float acc[NB][4]) {
    const int arow  = lane & 15;
    const int acolo = (lane >> 4) * 8;
    const int brow  = ((lane >> 4) << 3) + (lane & 7);
    const int bcolo = ((lane >> 3) & 1) * 8;
    #pragma unroll
    for (int kc = 0; kc < KC; kc++) {
        uint32_t a[4];
        ldsm4(a, Ab + qkoff(r0 + arow, kc * 16 + acolo));
        #pragma unroll
        for (int j = 0; j < NB / 2; j++) {
            uint32_t b[4];
            ldsm4(b, Bb + (uint32_t)((c0 + j * 16 + brow) * bstride + (kc * 16 + bcolo) * 2));
            mma16816(acc[j * 2 + 0], a, b[0], b[1]);
            mma16816(acc[j * 2 + 1], a, b[2], b[3]);
        }
    }
}

extern __shared__ __align__(16) char smem[];

__global__ void __launch_bounds__(THREADS, 2)
attn_hmma_kernel(const float* __restrict__ q,
                 const float* __restrict__ keys,
                 const float* __restrict__ ktc,
                 const float* __restrict__ values,
                 const float* __restrict__ vc,
                 const float* __restrict__ kqs,
                 float* __restrict__ out)
{
    const uint32_t sb = smem_u32(smem);
    const int tid  = threadIdx.x;
    const int w    = tid >> 5;
    const int lane = tid & 31;
    const int wr   = w & 3;           // 4 row groups of 16 rows
    const int wcol = w >> 2;          // 2 col groups
    const int r0   = wr * 16;
    const int c0s  = wcol * 32;       // QK: 32 score-cols per warp
    const int c0v  = wcol * 64;       // PV: 64 out-dims per warp
    const int h    = blockIdx.y;
    const int kv   = h / GROUP;
    const int m0   = blockIdx.x * BM;
    const float scale = kqs[0];

    const float* qbase    = q      + ((long)h * BATCH + m0) * HEAD_DIM;
    const float* ktc_base = ktc    + (long)kv * HEAD_DIM * CACHE;
    const float* vc_base  = vc     + (long)kv * CACHE * HEAD_DIM;
    const float* k_base   = keys   + (long)kv * BATCH * HEAD_DIM;
    const float* v_base   = values + (long)kv * BATCH * HEAD_DIM;

    float* lrow = (float*)(smem + OFF_L);
    if (tid < BM) lrow[tid] = 0.0f;

    // ---- load Q (64 x 128) split into QHI/QLO ----
    for (int i = tid; i < 2048; i += THREADS) {
        int r  = i >> 5;
        int d4 = (i & 31) << 2;
        float4 v = *(const float4*)(qbase + (long)r * HEAD_DIM + d4);
        uint32_t h0, l0, h1, l1;
        split_pair(v.x, v.y, h0, l0);
        split_pair(v.z, v.w, h1, l1);
        uint32_t o = qkoff(r, d4);
        *(uint32_t*)(smem + OFF_QHI + o)     = h0;
        *(uint32_t*)(smem + OFF_QHI + o + 4) = h1;
        *(uint32_t*)(smem + OFF_QLO + o)     = l0;
        *(uint32_t*)(smem + OFF_QLO + o + 4) = l1;
    }

    float oacc[8][4];
    #pragma unroll
    for (int nt = 0; nt < 8; nt++)
        #pragma unroll
        for (int k = 0; k < 4; k++) oacc[nt][k] = 0.0f;

    const int ntiles = (CACHE + m0 + BM) / BN;

    for (int t = 0; t < ntiles; t++) {
        const int c0t = t * BN;
        const bool is_new = (t >= CACHE / BN);

        // ---- stage K (64 ctx-cols x 128 d) and V (128 d x 64 ctx-cols) as split bf16 ----
        if (!is_new) {
            // K cache [d][2048] -> K[col][d], pack (d, d+1)
            for (int i = tid; i < 4096; i += THREADS) {
                int col = i & 63;
                int d   = (i >> 6) << 1;
                float a = ktc_base[(long)d * CACHE + c0t + col];
                float b = ktc_base[(long)(d + 1) * CACHE + c0t + col];
                uint32_t hi, lo;
                split_pair(a, b, hi, lo);
                uint32_t o = qkoff(col, d);
                *(uint32_t*)(smem + OFF_KHI + o) = hi;
                *(uint32_t*)(smem + OFF_KLO + o) = lo;
            }
            // V cache [c][d] -> V[d][c], pack (c, c+1)
            for (int i = tid; i < 4096; i += THREADS) {
                int d = i & 127;
                int c = (i >> 7) << 1;
                float a = vc_base[(long)(c0t + c) * HEAD_DIM + d];
                float b = vc_base[(long)(c0t + c + 1) * HEAD_DIM + d];
                uint32_t hi, lo;
                split_pair(a, b, hi, lo);
                uint32_t o = voff(d, c);
                *(uint32_t*)(smem + OFF_VHI + o) = hi;
                *(uint32_t*)(smem + OFF_VLO + o) = lo;
            }
        } else {
            const int j0 = c0t - CACHE;
            // new keys [b][d] (scaled) -> K[col][d]
            for (int i = tid; i < 2048; i += THREADS) {
                int r  = i >> 5;
                int d4 = (i & 31) << 2;
                float4 v = *(const float4*)(k_base + (long)(j0 + r) * HEAD_DIM + d4);
                v.x *= scale; v.y *= scale; v.z *= scale; v.w *= scale;
                uint32_t h0, l0, h1, l1;
                split_pair(v.x, v.y, h0, l0);
                split_pair(v.z, v.w, h1, l1);
                uint32_t o = qkoff(r, d4);
                *(uint32_t*)(smem + OFF_KHI + o)     = h0;
                *(uint32_t*)(smem + OFF_KHI + o + 4) = h1;
                *(uint32_t*)(smem + OFF_KLO + o)     = l0;
                *(uint32_t*)(smem + OFF_KLO + o + 4) = l1;
            }
            // new values [b][d] -> V[d][col] (clamped)
            for (int i = tid; i < 4096; i += THREADS) {
                int d = i & 127;
                int c = (i >> 7) << 1;
                float a = v_base[(long)(j0 + c) * HEAD_DIM + d];
                float b = v_base[(long)(j0 + c + 1) * HEAD_DIM + d];
                a = fmaxf(a, NEG_INF);
                b = fmaxf(b, NEG_INF);
                uint32_t hi, lo;
                split_pair(a, b, hi, lo);
                uint32_t o = voff(d, c);
                *(uint32_t*)(smem + OFF_VHI + o) = hi;
                *(uint32_t*)(smem + OFF_VLO + o) = lo;
            }
        }
        __syncthreads();

        // ---- QK^T: S = Qh*Kh + Qh*Kl + Ql*Kh  (M=64, N=64, K=128; warp tile 16x32) ----
        float sacc[4][4];
        #pragma unroll
        for (int nt = 0; nt < 4; nt++)
            #pragma unroll
            for (int k = 0; k < 4; k++) sacc[nt][k] = 0.0f;

        gemm16<8, 4>(sb + OFF_QHI, sb + OFF_KHI, QK_STRIDE, r0, c0s, lane, sacc);
        gemm16<8, 4>(sb + OFF_QHI, sb + OFF_KLO, QK_STRIDE, r0, c0s, lane, sacc);
        gemm16<8, 4>(sb + OFF_QLO, sb + OFF_KHI, QK_STRIDE, r0, c0s, lane, sacc);

        __syncthreads();   // all warps done reading K before P overwrites it

        // ---- epilogue: p = exp(s - M_REF), causal mask, row sums, split-P -> K buffers ----
        {
            const int ra = r0 + (lane >> 2);
            const int rb = ra + 8;
            float lpa = 0.f, lpb = 0.f;
            #pragma unroll
            for (int nt = 0; nt < 4; nt++) {
                const int cc = c0s + nt * 8 + ((lane & 3) << 1);
                float p0 = __expf(sacc[nt][0] - M_REF);
                float p1 = __expf(sacc[nt][1] - M_REF);
                float p2 = __expf(sacc[nt][2] - M_REF);
                float p3 = __expf(sacc[nt][3] - M_REF);
                if (is_new) {
                    const int j = c0t - CACHE + cc;
                    if (j     > m0 + ra) p0 = 0.f;
                    if (j + 1 > m0 + ra) p1 = 0.f;
                    if (j     > m0 + rb) p2 = 0.f;
                    if (j + 1 > m0 + rb) p3 = 0.f;
                }
                lpa += p0 + p1;
                lpb += p2 + p3;
                uint32_t hi, lo;
                split_pair(p0, p1, hi, lo);
                *(uint32_t*)(smem + OFF_KHI + qkoff(ra, cc)) = hi;
                *(uint32_t*)(smem + OFF_KLO + qkoff(ra, cc)) = lo;
                split_pair(p2, p3, hi, lo);
                *(uint32_t*)(smem + OFF_KHI + qkoff(rb, cc)) = hi;
                *(uint32_t*)(smem + OFF_KLO + qkoff(rb, cc)) = lo;
            }
            lpa += __shfl_xor_sync(0xffffffffu, lpa, 1);
            lpa += __shfl_xor_sync(0xffffffffu, lpa, 2);
            lpb += __shfl_xor_sync(0xffffffffu, lpb, 1);
            lpb += __shfl_xor_sync(0xffffffffu, lpb, 2);
            if ((lane & 3) == 0) {
                atomicAdd(&lrow[ra], lpa);
                atomicAdd(&lrow[rb], lpb);
            }
        }
        __syncthreads();   // P visible to all warps

        // ---- PV: O += Ph*Vh + Ph*Vl + Pl*Vh  (M=64, N=128, K=64; warp tile 16x64) ----
        gemm16<4, 8>(sb + OFF_KHI, sb + OFF_VHI, V_STRIDE, r0, c0v, lane, oacc);
        gemm16<4, 8>(sb + OFF_KHI, sb + OFF_VLO, V_STRIDE, r0, c0v, lane, oacc);
        gemm16<4, 8>(sb + OFF_KLO, sb + OFF_VHI, V_STRIDE, r0, c0v, lane, oacc);

        __syncthreads();   // protect K/V/P before next tile's staging
    }

    // ---- finalize: out = O / l ----
    {
        const int ra = r0 + (lane >> 2);
        const int rb = ra + 8;
        const float la = 1.0f / lrow[ra];
        const float lb = 1.0f / lrow[rb];
        #pragma unroll
        for (int nt = 0; nt < 8; nt++) {
            const int dc = c0v + nt * 8 + ((lane & 3) << 1);
            float* pa = out + ((long)h * BATCH + m0 + ra) * HEAD_DIM + dc;
            float* pb = out + ((long)h * BATCH + m0 + rb) * HEAD_DIM + dc;
            *(float2*)pa = make_float2(oacc[nt][0] * la, oacc[nt][1] * la);
            *(float2*)pb = make_float2(oacc[nt][2] * lb, oacc[nt][3] * lb);
        }
    }
}

__global__ void scale_kv_kernel(const float* __restrict__ keys,
                                const float* __restrict__ values,
                                const float* __restrict__ kqs,
                                float* __restrict__ out_sk,
                                float* __restrict__ out_sv, int n)
{
    int i = blockIdx.x * blockDim.x + threadIdx.x;
    if (i < n) {
        float sc = kqs[0];
        out_sk[i] = keys[i] * sc;
        out_sv[i] = fmaxf(values[i], NEG_INF);
    }
}

extern "C" void kernel_launch(void* const* d_in, const int* in_sizes, int n_in,
                              void* d_out, int out_size)
{
    const float* q      = (const float*)d_in[0];
    const float* keys   = (const float*)d_in[1];
    const float* ktc    = (const float*)d_in[2];
    const float* values = (const float*)d_in[3];
    const float* vc     = (const float*)d_in[4];
    // d_in[5] = attn_bias: analytic causal mask, not needed
    const float* kqs    = (const float*)d_in[6];

    float* out    = (float*)d_out;
    float* out_sk = out    + (long)NHEADS * BATCH * HEAD_DIM;
    float* out_sv = out_sk + (long)NKV    * BATCH * HEAD_DIM;

    cudaFuncSetAttribute(attn_hmma_kernel, cudaFuncAttributeMaxDynamicSharedMemorySize, SMEM_TOTAL);

    const int n_kv_elems = NKV * BATCH * HEAD_DIM;
    scale_kv_kernel<<<(n_kv_elems + 255) / 256, 256>>>(keys, values, kqs, out_sk, out_sv, n_kv_elems);

    dim3 grid(BATCH / BM, NHEADS);
    attn_hmma_kernel<<<grid, THREADS, SMEM_TOTAL>>>(q, keys, ktc, values, vc, kqs, out);
}

// round 10
// speedup vs baseline: 1.4439x; 1.4439x over previous
#include <cuda_runtime.h>
#include <cuda_bf16.h>
#include <cstdint>

#define NKV      8
#define GROUP    4
#define NHEADS   32
#define BATCH    512
#define HEAD_DIM 128
#define CACHE    2048
#define CTX      2560              // CACHE + BATCH
#define NEG_INF  (-10000.0f)
#define M_REF    40.0f
#define THREADS  256
#define BM       128
#define BN       64

// ---- global pre-split K/V (bf16 hi/lo) ----
// Kg*: [kv][col 2560][d 128]  (QK B operand, k-major rows)
// Vg*: [kv][d 128][col 2560]  (PV B operand)
__device__ __nv_bfloat16 KgHi[(long)NKV * CTX * HEAD_DIM];
__device__ __nv_bfloat16 KgLo[(long)NKV * CTX * HEAD_DIM];
__device__ __nv_bfloat16 VgHi[(long)NKV * HEAD_DIM * CTX];
__device__ __nv_bfloat16 VgLo[(long)NKV * HEAD_DIM * CTX];

// ---- smem layout (main kernel) ----
#define QK_STRIDE 272              // 128 k-dim bf16 + 16B pad
#define P_STRIDE  144              // 64 cols bf16 + 16B pad (16B-aligned rows)
#define OFF_L    0                 // float lrow[128]
#define OFF_QHI  512
#define OFF_QLO  (OFF_QHI + 34816)     // 128*272
#define OFF_K0H  (OFF_QLO + 34816)
#define OFF_K0L  (OFF_K0H + 17408)     // 64*272
#define OFF_K1H  (OFF_K0L + 17408)
#define OFF_K1L  (OFF_K1H + 17408)
#define OFF_VH   (OFF_K1L + 17408)
#define OFF_VL   (OFF_VH  + 18432)     // 128*144
#define OFF_PH   (OFF_VL  + 18432)
#define OFF_PL   (OFF_PH  + 18432)
#define SMEM_TOTAL (OFF_PL + 18432)    // 213504 bytes

__device__ __forceinline__ uint32_t smem_u32(const void* p) {
    uint32_t a;
    asm("{ .reg .u64 t; cvta.to.shared.u64 t, %1; cvt.u32.u64 %0, t; }" : "=r"(a) : "l"(p));
    return a;
}
__device__ __forceinline__ void ldsm4(uint32_t* r, uint32_t addr) {
    asm volatile("ldmatrix.sync.aligned.m8n8.x4.shared.b16 {%0,%1,%2,%3}, [%4];"
                 : "=r"(r[0]), "=r"(r[1]), "=r"(r[2]), "=r"(r[3]) : "r"(addr));
}
__device__ __forceinline__ void mma16816(float* c, const uint32_t* a, uint32_t b0, uint32_t b1) {
    asm volatile("mma.sync.aligned.m16n8k16.row.col.f32.bf16.bf16.f32 "
                 "{%0,%1,%2,%3}, {%4,%5,%6,%7}, {%8,%9}, {%0,%1,%2,%3};"
                 : "+f"(c[0]), "+f"(c[1]), "+f"(c[2]), "+f"(c[3])
                 : "r"(a[0]), "r"(a[1]), "r"(a[2]), "r"(a[3]), "r"(b0), "r"(b1));
}
__device__ __forceinline__ void cpa16(uint32_t s, const void* g) {
    asm volatile("{ .reg .u64 ga; cvta.to.global.u64 ga, %1; cp.async.ca.shared.global [%0], [ga], 16; }"
                 :: "r"(s), "l"(g) : "memory");
}
__device__ __forceinline__ void cp_commit() { asm volatile("cp.async.commit_group;" ::: "memory"); }
__device__ __forceinline__ void cp_wait1()  { asm volatile("cp.async.wait_group 1;"  ::: "memory"); }
__device__ __forceinline__ void cp_wait0()  { asm volatile("cp.async.wait_group 0;"  ::: "memory"); }

__device__ __forceinline__ uint32_t bpack(float a, float b) {
    __nv_bfloat162 t = __floats2bfloat162_rn(a, b);
    return *reinterpret_cast<uint32_t*>(&t);
}
__device__ __forceinline__ void split_pair(float a, float b, uint32_t& hi, uint32_t& lo) {
    float ah = __bfloat162float(__float2bfloat16(a));
    float bh = __bfloat162float(__float2bfloat16(b));
    hi = bpack(ah, bh);
    lo = bpack(a - ah, b - bh);
}
__device__ __forceinline__ void split1(float v, __nv_bfloat16& hi, __nv_bfloat16& lo) {
    hi = __float2bfloat16(v);
    lo = __float2bfloat16(v - __bfloat162float(hi));
}

// MMA pass: A rows r0..r0+31 (astride), B rows c0..c0+NP*16-1 (bstride), K = KC*16.
// acc[2][NP*2][4].
template<int KC, int NP>
__device__ __forceinline__ void gemm_pass(uint32_t Ab, int astride, uint32_t Bb, int bstride,
                                          int r0, int c0, int lane, float acc[2][NP * 2][4]) {
    const int arow  = lane & 15;
    const int acolo = (lane >> 4) * 8;
    const int brow  = ((lane >> 4) << 3) + (lane & 7);
    const int bcolo = ((lane >> 3) & 1) * 8;
    #pragma unroll
    for (int kc = 0; kc < KC; kc++) {
        uint32_t a0[4], a1[4];
        ldsm4(a0, Ab + (uint32_t)((r0 + arow) * astride + (kc * 16 + acolo) * 2));
        ldsm4(a1, Ab + (uint32_t)((r0 + 16 + arow) * astride + (kc * 16 + acolo) * 2));
        #pragma unroll
        for (int np = 0; np < NP; np++) {
            uint32_t b[4];
            ldsm4(b, Bb + (uint32_t)((c0 + np * 16 + brow) * bstride + (kc * 16 + bcolo) * 2));
            mma16816(acc[0][np * 2 + 0], a0, b[0], b[1]);
            mma16816(acc[0][np * 2 + 1], a0, b[2], b[3]);
            mma16816(acc[1][np * 2 + 0], a1, b[0], b[1]);
            mma16816(acc[1][np * 2 + 1], a1, b[2], b[3]);
        }
    }
}

// ============ pre-pass: build split K (and scaled_keys output) ============
__global__ void prep_k(const float* __restrict__ ktc, const float* __restrict__ keys,
                       const float* __restrict__ kqs, float* __restrict__ out_sk)
{
    const int kv = blockIdx.z;
    const int c0 = blockIdx.x * 32;
    const int d0 = blockIdx.y * 32;
    const int tx = threadIdx.x, ty = threadIdx.y;
    __shared__ float tile[32][33];

    if (c0 < CACHE) {
        // transpose ktc[kv][d][c] -> Kg[kv][c][d]
        #pragma unroll
        for (int i = 0; i < 4; i++) {
            int d = d0 + ty + i * 8;
            tile[ty + i * 8][tx] = ktc[((long)kv * HEAD_DIM + d) * CACHE + c0 + tx];
        }
        __syncthreads();
        #pragma unroll
        for (int i = 0; i < 4; i++) {
            int c = c0 + ty + i * 8;
            int d = d0 + tx;
            float v = tile[tx][ty + i * 8];        // [d_local][c_local]
            __nv_bfloat16 hi, lo;
            split1(v, hi, lo);
            long o = ((long)kv * CTX + c) * HEAD_DIM + d;
            KgHi[o] = hi; KgLo[o] = lo;
        }
    } else {
        const float s = kqs[0];
        const int b0 = c0 - CACHE;
        #pragma unroll
        for (int i = 0; i < 4; i++) {
            int b = b0 + ty + i * 8;
            int d = d0 + tx;
            float v = keys[((long)kv * BATCH + b) * HEAD_DIM + d] * s;
            out_sk[((long)kv * BATCH + b) * HEAD_DIM + d] = v;
            __nv_bfloat16 hi, lo;
            split1(v, hi, lo);
            long o = ((long)kv * CTX + CACHE + b) * HEAD_DIM + d;
            KgHi[o] = hi; KgLo[o] = lo;
        }
    }
}

// ============ pre-pass: build split V (and scaled_values output) ============
__global__ void prep_v(const float* __restrict__ vc, const float* __restrict__ values,
                       float* __restrict__ out_sv)
{
    const int kv = blockIdx.z;
    const int c0 = blockIdx.x * 32;
    const int d0 = blockIdx.y * 32;
    const int tx = threadIdx.x, ty = threadIdx.y;
    __shared__ float tile[32][33];   // [c_local][d_local]

    if (c0 < CACHE) {
        #pragma unroll
        for (int i = 0; i < 4; i++) {
            int c = c0 + ty + i * 8;
            tile[ty + i * 8][tx] = vc[((long)kv * CACHE + c) * HEAD_DIM + d0 + tx];
        }
    } else {
        const int b0 = c0 - CACHE;
        #pragma unroll
        for (int i = 0; i < 4; i++) {
            int b = b0 + ty + i * 8;
            float v = fmaxf(values[((long)kv * BATCH + b) * HEAD_DIM + d0 + tx], NEG_INF);
            tile[ty + i * 8][tx] = v;
            out_sv[((long)kv * BATCH + b) * HEAD_DIM + d0 + tx] = v;
        }
    }
    __syncthreads();
    #pragma unroll
    for (int i = 0; i < 4; i++) {
        int d = d0 + ty + i * 8;
        int c = c0 + tx;
        float v = tile[tx][ty + i * 8];
        __nv_bfloat16 hi, lo;
        split1(v, hi, lo);
        long o = ((long)kv * HEAD_DIM + d) * CTX + c;
        VgHi[o] = hi; VgLo[o] = lo;
    }
}

// ============ main attention kernel ============
extern __shared__ __align__(16) char smem[];

__device__ __forceinline__ void stage_k(uint32_t sb, int buf, int kv, int C, int tid) {
    const __nv_bfloat16* gh = KgHi + ((long)kv * CTX + C) * HEAD_DIM;
    const __nv_bfloat16* gl = KgLo + ((long)kv * CTX + C) * HEAD_DIM;
    const uint32_t sh = sb + (buf ? OFF_K1H : OFF_K0H);
    const uint32_t sl = sb + (buf ? OFF_K1L : OFF_K0L);
    #pragma unroll
    for (int i = 0; i < 4; i++) {
        int idx = tid + i * THREADS;        // 1024 chunks per array
        int r = idx >> 4, ch = idx & 15;
        cpa16(sh + r * QK_STRIDE + ch * 16, gh + r * HEAD_DIM + ch * 8);
        cpa16(sl + r * QK_STRIDE + ch * 16, gl + r * HEAD_DIM + ch * 8);
    }
}
__device__ __forceinline__ void stage_v(uint32_t sb, int kv, int C, int tid) {
    const __nv_bfloat16* gh = VgHi + (long)kv * HEAD_DIM * CTX + C;
    const __nv_bfloat16* gl = VgLo + (long)kv * HEAD_DIM * CTX + C;
    #pragma unroll
    for (int i = 0; i < 4; i++) {
        int idx = tid + i * THREADS;        // 1024 chunks per array
        int r = idx >> 3, ch = idx & 7;
        cpa16(sb + OFF_VH + r * P_STRIDE + ch * 16, gh + (long)r * CTX + ch * 8);
        cpa16(sb + OFF_VL + r * P_STRIDE + ch * 16, gl + (long)r * CTX + ch * 8);
    }
}

__global__ void __launch_bounds__(THREADS)
attn_hmma_kernel(const float* __restrict__ q,
                 const float* __restrict__ kqs,
                 float* __restrict__ out)
{
    const uint32_t sb = smem_u32(smem);
    const int tid  = threadIdx.x;
    const int w    = tid >> 5;
    const int lane = tid & 31;
    const int wr   = w & 3;            // 4 row groups of 32 rows
    const int wc   = w >> 2;           // 2 col groups
    const int r0   = wr * 32;
    const int c0s  = wc * 32;          // QK: 32 score-cols per warp
    const int c0v  = wc * 64;          // PV: 64 out-dims per warp
    const int h    = blockIdx.y;
    const int kv   = h / GROUP;
    const int m0   = blockIdx.x * BM;

    const float* qbase = q + ((long)h * BATCH + m0) * HEAD_DIM;

    float* lrow = (float*)(smem + OFF_L);
    if (tid < BM) lrow[tid] = 0.0f;

    // prologue prefetch: K(0), V(0)
    stage_k(sb, 0, kv, 0, tid); cp_commit();
    stage_v(sb, kv, 0, tid);    cp_commit();

    // ---- load Q (128 x 128) split into QHI/QLO ----
    for (int i = tid; i < 4096; i += THREADS) {
        int r  = i >> 5;
        int d4 = (i & 31) << 2;
        float4 v = *(const float4*)(qbase + (long)r * HEAD_DIM + d4);
        uint32_t h0, l0, h1, l1;
        split_pair(v.x, v.y, h0, l0);
        split_pair(v.z, v.w, h1, l1);
        uint32_t o = (uint32_t)(r * QK_STRIDE + d4 * 2);
        *(uint32_t*)(smem + OFF_QHI + o)     = h0;
        *(uint32_t*)(smem + OFF_QHI + o + 4) = h1;
        *(uint32_t*)(smem + OFF_QLO + o)     = l0;
        *(uint32_t*)(smem + OFF_QLO + o + 4) = l1;
    }

    float oacc[2][8][4];
    #pragma unroll
    for (int mt = 0; mt < 2; mt++)
        #pragma unroll
        for (int nt = 0; nt < 8; nt++)
            #pragma unroll
            for (int k = 0; k < 4; k++) oacc[mt][nt][k] = 0.0f;

    const int ntiles = (CACHE + m0 + BM) / BN;

    for (int t = 0; t < ntiles; t++) {
        const int C = t * BN;
        const bool is_new = (C >= CACHE);
        const int buf = t & 1;
        const uint32_t KH = sb + (buf ? OFF_K1H : OFF_K0H);
        const uint32_t KL = sb + (buf ? OFF_K1L : OFF_K0L);

        // wait K(t) ready (V(t) may still be in flight)
        cp_wait1();
        __syncthreads();

        // ---- QK^T: S = Qh*Kh + Qh*Kl + Ql*Kh  (M=128, N=64, K=128; warp 32x32) ----
        float sacc[2][4][4];
        #pragma unroll
        for (int mt = 0; mt < 2; mt++)
            #pragma unroll
            for (int nt = 0; nt < 4; nt++)
                #pragma unroll
                for (int k = 0; k < 4; k++) sacc[mt][nt][k] = 0.0f;

        gemm_pass<8, 2>(sb + OFF_QHI, QK_STRIDE, KH, QK_STRIDE, r0, c0s, lane, sacc);
        gemm_pass<8, 2>(sb + OFF_QHI, QK_STRIDE, KL, QK_STRIDE, r0, c0s, lane, sacc);
        gemm_pass<8, 2>(sb + OFF_QLO, QK_STRIDE, KH, QK_STRIDE, r0, c0s, lane, sacc);

        __syncthreads();   // K(t) reads done -> its buffer is free for K(t+1)

        if (t + 1 < ntiles) { stage_k(sb, buf ^ 1, kv, C + BN, tid); cp_commit(); }

        // ---- epilogue: p = exp(s - M_REF), causal mask, row sums, split-P ----
        {
            #pragma unroll
            for (int mt = 0; mt < 2; mt++) {
                const int ra = r0 + mt * 16 + (lane >> 2);
                const int rb = ra + 8;
                float lpa = 0.f, lpb = 0.f;
                #pragma unroll
                for (int nt = 0; nt < 4; nt++) {
                    const int cc = c0s + nt * 8 + ((lane & 3) << 1);
                    float p0 = __expf(sacc[mt][nt][0] - M_REF);
                    float p1 = __expf(sacc[mt][nt][1] - M_REF);
                    float p2 = __expf(sacc[mt][nt][2] - M_REF);
                    float p3 = __expf(sacc[mt][nt][3] - M_REF);
                    if (is_new) {
                        const int j = C - CACHE + cc;
                        if (j     > m0 + ra) p0 = 0.f;
                        if (j + 1 > m0 + ra) p1 = 0.f;
                        if (j     > m0 + rb) p2 = 0.f;
                        if (j + 1 > m0 + rb) p3 = 0.f;
                    }
                    lpa += p0 + p1;
                    lpb += p2 + p3;
                    uint32_t hi, lo;
                    split_pair(p0, p1, hi, lo);
                    *(uint32_t*)(smem + OFF_PH + ra * P_STRIDE + cc * 2) = hi;
                    *(uint32_t*)(smem + OFF_PL + ra * P_STRIDE + cc * 2) = lo;
                    split_pair(p2, p3, hi, lo);
                    *(uint32_t*)(smem + OFF_PH + rb * P_STRIDE + cc * 2) = hi;
                    *(uint32_t*)(smem + OFF_PL + rb * P_STRIDE + cc * 2) = lo;
                }
                lpa += __shfl_xor_sync(0xffffffffu, lpa, 1);
                lpa += __shfl_xor_sync(0xffffffffu, lpa, 2);
                lpb += __shfl_xor_sync(0xffffffffu, lpb, 1);
                lpb += __shfl_xor_sync(0xffffffffu, lpb, 2);
                if ((lane & 3) == 0) {
                    atomicAdd(&lrow[ra], lpa);
                    atomicAdd(&lrow[rb], lpb);
                }
            }
        }

        // wait V(t) ready (K(t+1) may still be in flight), publish P
        if (t + 1 < ntiles) cp_wait1(); else cp_wait0();
        __syncthreads();

        // ---- PV: O += Ph*Vh + Ph*Vl + Pl*Vh  (M=128, N=128, K=64; warp 32x64) ----
        gemm_pass<4, 4>(sb + OFF_PH, P_STRIDE, sb + OFF_VH, P_STRIDE, r0, c0v, lane, oacc);
        gemm_pass<4, 4>(sb + OFF_PH, P_STRIDE, sb + OFF_VL, P_STRIDE, r0, c0v, lane, oacc);
        gemm_pass<4, 4>(sb + OFF_PL, P_STRIDE, sb + OFF_VH, P_STRIDE, r0, c0v, lane, oacc);

        __syncthreads();   // V(t)/P reads done -> V buffer free for V(t+1)

        if (t + 1 < ntiles) { stage_v(sb, kv, C + BN, tid); cp_commit(); }
    }

    // ---- finalize: out = O / l ----
    #pragma unroll
    for (int mt = 0; mt < 2; mt++) {
        const int ra = r0 + mt * 16 + (lane >> 2);
        const int rb = ra + 8;
        const float la = 1.0f / lrow[ra];
        const float lb = 1.0f / lrow[rb];
        #pragma unroll
        for (int nt = 0; nt < 8; nt++) {
            const int dc = c0v + nt * 8 + ((lane & 3) << 1);
            float* pa = out + ((long)h * BATCH + m0 + ra) * HEAD_DIM + dc;
            float* pb = out + ((long)h * BATCH + m0 + rb) * HEAD_DIM + dc;
            *(float2*)pa = make_float2(oacc[mt][nt][0] * la, oacc[mt][nt][1] * la);
            *(float2*)pb = make_float2(oacc[mt][nt][2] * lb, oacc[mt][nt][3] * lb);
        }
    }
}

extern "C" void kernel_launch(void* const* d_in, const int* in_sizes, int n_in,
                              void* d_out, int out_size)
{
    const float* q      = (const float*)d_in[0];
    const float* keys   = (const float*)d_in[1];
    const float* ktc    = (const float*)d_in[2];
    const float* values = (const float*)d_in[3];
    const float* vc     = (const float*)d_in[4];
    // d_in[5] = attn_bias: analytic causal mask, not needed
    const float* kqs    = (const float*)d_in[6];

    float* out    = (float*)d_out;
    float* out_sk = out    + (long)NHEADS * BATCH * HEAD_DIM;
    float* out_sv = out_sk + (long)NKV    * BATCH * HEAD_DIM;

    cudaFuncSetAttribute(attn_hmma_kernel, cudaFuncAttributeMaxDynamicSharedMemorySize, SMEM_TOTAL);

    dim3 pgrid(CTX / 32, HEAD_DIM / 32, NKV);
    dim3 pblk(32, 8);
    prep_k<<<pgrid, pblk>>>(ktc, keys, kqs, out_sk);
    prep_v<<<pgrid, pblk>>>(vc, values, out_sv);

    dim3 grid(BATCH / BM, NHEADS);
    attn_hmma_kernel<<<grid, THREADS, SMEM_TOTAL>>>(q, kqs, out);
}

// round 11
// speedup vs baseline: 1.5288x; 1.0588x over previous
#include <cuda_runtime.h>
#include <cuda_bf16.h>
#include <cstdint>

#define NKV      8
#define GROUP    4
#define NHEADS   32
#define BATCH    512
#define HEAD_DIM 128
#define CACHE    2048
#define CTX      2560
#define NEG_INF  (-10000.0f)
#define M_REF    40.0f
#define THREADS  256
#define BM       128
#define BN       64

// ---- global pre-split K/V (bf16 hi/lo) ----
__device__ __nv_bfloat16 KgHi[(long)NKV * CTX * HEAD_DIM];   // [kv][col][d]
__device__ __nv_bfloat16 KgLo[(long)NKV * CTX * HEAD_DIM];
__device__ __nv_bfloat16 VgHi[(long)NKV * HEAD_DIM * CTX];   // [kv][d][col]
__device__ __nv_bfloat16 VgLo[(long)NKV * HEAD_DIM * CTX];

// ---- smem layout ----
#define QK_STRIDE 272              // 128 k bf16 + 16B pad
#define V_STRIDE  144              // 64 k bf16 + 16B pad
#define OFF_L    0
#define OFF_QHI  512
#define OFF_QLO  (OFF_QHI + 34816)
#define OFF_K0H  (OFF_QLO + 34816)
#define OFF_K0L  (OFF_K0H + 17408)
#define OFF_K1H  (OFF_K0L + 17408)
#define OFF_K1L  (OFF_K1H + 17408)
#define OFF_V0H  (OFF_K1L + 17408)
#define OFF_V0L  (OFF_V0H + 18432)
#define OFF_V1H  (OFF_V0L + 18432)
#define OFF_V1L  (OFF_V1H + 18432)
#define SMEM_TOTAL (OFF_V1L + 18432)   // 213504

__device__ __forceinline__ uint32_t smem_u32(const void* p) {
    uint32_t a;
    asm("{ .reg .u64 t; cvta.to.shared.u64 t, %1; cvt.u32.u64 %0, t; }" : "=r"(a) : "l"(p));
    return a;
}
__device__ __forceinline__ void ldsm4(uint32_t* r, uint32_t addr) {
    asm volatile("ldmatrix.sync.aligned.m8n8.x4.shared.b16 {%0,%1,%2,%3}, [%4];"
                 : "=r"(r[0]), "=r"(r[1]), "=r"(r[2]), "=r"(r[3]) : "r"(addr));
}
__device__ __forceinline__ void mma16816(float* c, const uint32_t* a, uint32_t b0, uint32_t b1) {
    asm volatile("mma.sync.aligned.m16n8k16.row.col.f32.bf16.bf16.f32 "
                 "{%0,%1,%2,%3}, {%4,%5,%6,%7}, {%8,%9}, {%0,%1,%2,%3};"
                 : "+f"(c[0]), "+f"(c[1]), "+f"(c[2]), "+f"(c[3])
                 : "r"(a[0]), "r"(a[1]), "r"(a[2]), "r"(a[3]), "r"(b0), "r"(b1));
}
__device__ __forceinline__ void cpa16(uint32_t s, const void* g) {
    asm volatile("{ .reg .u64 ga; cvta.to.global.u64 ga, %1; cp.async.ca.shared.global [%0], [ga], 16; }"
                 :: "r"(s), "l"(g) : "memory");
}
__device__ __forceinline__ void cp_commit() { asm volatile("cp.async.commit_group;" ::: "memory"); }
__device__ __forceinline__ void cp_wait0()  { asm volatile("cp.async.wait_group 0;"  ::: "memory"); }

__device__ __forceinline__ uint32_t bpack(float a, float b) {
    __nv_bfloat162 t = __floats2bfloat162_rn(a, b);
    return *reinterpret_cast<uint32_t*>(&t);
}
__device__ __forceinline__ void split_pair(float a, float b, uint32_t& hi, uint32_t& lo) {
    float ah = __bfloat162float(__float2bfloat16(a));
    float bh = __bfloat162float(__float2bfloat16(b));
    hi = bpack(ah, bh);
    lo = bpack(a - ah, b - bh);
}
__device__ __forceinline__ void split1(float v, __nv_bfloat16& hi, __nv_bfloat16& lo) {
    hi = __float2bfloat16(v);
    lo = __float2bfloat16(v - __bfloat162float(hi));
}

// QK pass: A rows r0..r0+31 (QK_STRIDE), B rows c0..c0+31 (QK_STRIDE), K=128. acc[2][4][4].
__device__ __forceinline__ void qk_pass(uint32_t Ab, uint32_t Bb, int r0, int c0,
                                        int lane, float acc[2][4][4]) {
    const int arow  = lane & 15;
    const int acolo = (lane >> 4) * 8;
    const int brow  = ((lane >> 4) << 3) + (lane & 7);
    const int bcolo = ((lane >> 3) & 1) * 8;
    #pragma unroll
    for (int kc = 0; kc < 8; kc++) {
        uint32_t a0[4], a1[4];
        ldsm4(a0, Ab + (uint32_t)((r0 + arow) * QK_STRIDE + (kc * 16 + acolo) * 2));
        ldsm4(a1, Ab + (uint32_t)((r0 + 16 + arow) * QK_STRIDE + (kc * 16 + acolo) * 2));
        #pragma unroll
        for (int np = 0; np < 2; np++) {
            uint32_t b[4];
            ldsm4(b, Bb + (uint32_t)((c0 + np * 16 + brow) * QK_STRIDE + (kc * 16 + bcolo) * 2));
            mma16816(acc[0][np * 2 + 0], a0, b[0], b[1]);
            mma16816(acc[0][np * 2 + 1], a0, b[2], b[3]);
            mma16816(acc[1][np * 2 + 0], a1, b[0], b[1]);
            mma16816(acc[1][np * 2 + 1], a1, b[2], b[3]);
        }
    }
}

// PV pass: A = P fragments in registers (pa[mt][8] packed bf16x2), B = V slice
// (k-cols kbase..kbase+31 within tile), O_part 32 rows x 128 d. acc[2][16][4].
__device__ __forceinline__ void pv_pass(const uint32_t pa[2][8], uint32_t Vb, int kbase,
                                        int lane, float acc[2][16][4]) {
    const int brow  = ((lane >> 4) << 3) + (lane & 7);
    const int bcolo = ((lane >> 3) & 1) * 8;
    #pragma unroll
    for (int kc = 0; kc < 2; kc++) {
        #pragma unroll
        for (int nb = 0; nb < 8; nb++) {
            uint32_t b[4];
            ldsm4(b, Vb + (uint32_t)((nb * 16 + brow) * V_STRIDE + (kbase + kc * 16 + bcolo) * 2));
            #pragma unroll
            for (int mt = 0; mt < 2; mt++) {
                mma16816(acc[mt][nb * 2 + 0], &pa[mt][kc * 4], b[0], b[1]);
                mma16816(acc[mt][nb * 2 + 1], &pa[mt][kc * 4], b[2], b[3]);
            }
        }
    }
}

// ============ pre-pass kernels (unchanged from R10) ============
__global__ void prep_k(const float* __restrict__ ktc, const float* __restrict__ keys,
                       const float* __restrict__ kqs, float* __restrict__ out_sk)
{
    const int kv = blockIdx.z;
    const int c0 = blockIdx.x * 32;
    const int d0 = blockIdx.y * 32;
    const int tx = threadIdx.x, ty = threadIdx.y;
    __shared__ float tile[32][33];

    if (c0 < CACHE) {
        #pragma unroll
        for (int i = 0; i < 4; i++) {
            int d = d0 + ty + i * 8;
            tile[ty + i * 8][tx] = ktc[((long)kv * HEAD_DIM + d) * CACHE + c0 + tx];
        }
        __syncthreads();
        #pragma unroll
        for (int i = 0; i < 4; i++) {
            int c = c0 + ty + i * 8;
            int d = d0 + tx;
            float v = tile[tx][ty + i * 8];
            __nv_bfloat16 hi, lo;
            split1(v, hi, lo);
            long o = ((long)kv * CTX + c) * HEAD_DIM + d;
            KgHi[o] = hi; KgLo[o] = lo;
        }
    } else {
        const float s = kqs[0];
        const int b0 = c0 - CACHE;
        #pragma unroll
        for (int i = 0; i < 4; i++) {
            int b = b0 + ty + i * 8;
            int d = d0 + tx;
            float v = keys[((long)kv * BATCH + b) * HEAD_DIM + d] * s;
            out_sk[((long)kv * BATCH + b) * HEAD_DIM + d] = v;
            __nv_bfloat16 hi, lo;
            split1(v, hi, lo);
            long o = ((long)kv * CTX + CACHE + b) * HEAD_DIM + d;
            KgHi[o] = hi; KgLo[o] = lo;
        }
    }
}

__global__ void prep_v(const float* __restrict__ vc, const float* __restrict__ values,
                       float* __restrict__ out_sv)
{
    const int kv = blockIdx.z;
    const int c0 = blockIdx.x * 32;
    const int d0 = blockIdx.y * 32;
    const int tx = threadIdx.x, ty = threadIdx.y;
    __shared__ float tile[32][33];

    if (c0 < CACHE) {
        #pragma unroll
        for (int i = 0; i < 4; i++) {
            int c = c0 + ty + i * 8;
            tile[ty + i * 8][tx] = vc[((long)kv * CACHE + c) * HEAD_DIM + d0 + tx];
        }
    } else {
        const int b0 = c0 - CACHE;
        #pragma unroll
        for (int i = 0; i < 4; i++) {
            int b = b0 + ty + i * 8;
            float v = fmaxf(values[((long)kv * BATCH + b) * HEAD_DIM + d0 + tx], NEG_INF);
            tile[ty + i * 8][tx] = v;
            out_sv[((long)kv * BATCH + b) * HEAD_DIM + d0 + tx] = v;
        }
    }
    __syncthreads();
    #pragma unroll
    for (int i = 0; i < 4; i++) {
        int d = d0 + ty + i * 8;
        int c = c0 + tx;
        float v = tile[tx][ty + i * 8];
        __nv_bfloat16 hi, lo;
        split1(v, hi, lo);
        long o = ((long)kv * HEAD_DIM + d) * CTX + c;
        VgHi[o] = hi; VgLo[o] = lo;
    }
}

// ============ main kernel ============
extern __shared__ __align__(16) char smem[];

__device__ __forceinline__ void stage_k(uint32_t sb, int buf, int kv, int C, int tid) {
    const __nv_bfloat16* gh = KgHi + ((long)kv * CTX + C) * HEAD_DIM;
    const __nv_bfloat16* gl = KgLo + ((long)kv * CTX + C) * HEAD_DIM;
    const uint32_t sh = sb + (buf ? OFF_K1H : OFF_K0H);
    const uint32_t sl = sb + (buf ? OFF_K1L : OFF_K0L);
    #pragma unroll
    for (int i = 0; i < 4; i++) {
        int idx = tid + i * THREADS;          // 1024 16B chunks each
        int r = idx >> 4, ch = idx & 15;
        cpa16(sh + r * QK_STRIDE + ch * 16, gh + r * HEAD_DIM + ch * 8);
        cpa16(sl + r * QK_STRIDE + ch * 16, gl + r * HEAD_DIM + ch * 8);
    }
}
__device__ __forceinline__ void stage_v(uint32_t sb, int buf, int kv, int C, int tid) {
    const __nv_bfloat16* gh = VgHi + (long)kv * HEAD_DIM * CTX + C;
    const __nv_bfloat16* gl = VgLo + (long)kv * HEAD_DIM * CTX + C;
    const uint32_t sh = sb + (buf ? OFF_V1H : OFF_V0H);
    const uint32_t sl = sb + (buf ? OFF_V1L : OFF_V0L);
    #pragma unroll
    for (int i = 0; i < 4; i++) {
        int idx = tid + i * THREADS;          // 1024 16B chunks each
        int r = idx >> 3, ch = idx & 7;
        cpa16(sh + r * V_STRIDE + ch * 16, gh + (long)r * CTX + ch * 8);
        cpa16(sl + r * V_STRIDE + ch * 16, gl + (long)r * CTX + ch * 8);
    }
}

__global__ void __launch_bounds__(THREADS, 1)
attn_hmma_kernel(const float* __restrict__ q,
                 float* __restrict__ out)
{
    const uint32_t sb = smem_u32(smem);
    const int tid  = threadIdx.x;
    const int w    = tid >> 5;
    const int lane = tid & 31;
    const int wr   = w & 3;            // 4 row groups of 32 rows
    const int wc   = w >> 2;           // 2 k-slice groups
    const int r0   = wr * 32;
    const int c0s  = wc * 32;          // this warp's 32 score-cols = its PV k-slice
    const int h    = blockIdx.y;
    const int kv   = h / GROUP;
    const int m0   = blockIdx.x * BM;

    const float* qbase = q + ((long)h * BATCH + m0) * HEAD_DIM;

    float* lrow = (float*)(smem + OFF_L);
    if (tid < BM) lrow[tid] = 0.0f;

    // prologue prefetch K(0)+V(0) as one group
    stage_k(sb, 0, kv, 0, tid);
    stage_v(sb, 0, kv, 0, tid);
    cp_commit();

    // ---- load Q (128x128) split into QHI/QLO ----
    for (int i = tid; i < 4096; i += THREADS) {
        int r  = i >> 5;
        int d4 = (i & 31) << 2;
        float4 v = *(const float4*)(qbase + (long)r * HEAD_DIM + d4);
        uint32_t h0, l0, h1, l1;
        split_pair(v.x, v.y, h0, l0);
        split_pair(v.z, v.w, h1, l1);
        uint32_t o = (uint32_t)(r * QK_STRIDE + d4 * 2);
        *(uint32_t*)(smem + OFF_QHI + o)     = h0;
        *(uint32_t*)(smem + OFF_QHI + o + 4) = h1;
        *(uint32_t*)(smem + OFF_QLO + o)     = l0;
        *(uint32_t*)(smem + OFF_QLO + o + 4) = l1;
    }

    float oacc[2][16][4];
    #pragma unroll
    for (int mt = 0; mt < 2; mt++)
        #pragma unroll
        for (int nb = 0; nb < 16; nb++)
            #pragma unroll
            for (int k = 0; k < 4; k++) oacc[mt][nb][k] = 0.0f;

    const int ntiles = (CACHE + m0 + BM) / BN;

    for (int t = 0; t < ntiles; t++) {
        const int C = t * BN;
        const bool is_new = (C >= CACHE);
        const int buf = t & 1;
        const uint32_t KH = sb + (buf ? OFF_K1H : OFF_K0H);
        const uint32_t KL = sb + (buf ? OFF_K1L : OFF_K0L);
        const uint32_t VH = sb + (buf ? OFF_V1H : OFF_V0H);
        const uint32_t VL = sb + (buf ? OFF_V1L : OFF_V0L);

        cp_wait0();          // K(t)+V(t) arrived (only group in flight)
        __syncthreads();     // visible to all; all warps done with buffers t-1

        if (t + 1 < ntiles) {
            stage_k(sb, buf ^ 1, kv, C + BN, tid);
            stage_v(sb, buf ^ 1, kv, C + BN, tid);
            cp_commit();
        }

        // ---- QK^T: S = Qh*Kh + Qh*Kl + Ql*Kh  (warp 32x32) ----
        float sacc[2][4][4];
        #pragma unroll
        for (int mt = 0; mt < 2; mt++)
            #pragma unroll
            for (int nt = 0; nt < 4; nt++)
                #pragma unroll
                for (int k = 0; k < 4; k++) sacc[mt][nt][k] = 0.0f;

        qk_pass(sb + OFF_QHI, KH, r0, c0s, lane, sacc);
        qk_pass(sb + OFF_QHI, KL, r0, c0s, lane, sacc);
        qk_pass(sb + OFF_QLO, KH, r0, c0s, lane, sacc);

        // ---- epilogue in registers: p = exp(s - M_REF), mask, lrow, pack P frags ----
        uint32_t phi[2][8], plo[2][8];
        #pragma unroll
        for (int mt = 0; mt < 2; mt++) {
            const int ra = r0 + mt * 16 + (lane >> 2);
            const int rb = ra + 8;
            float lpa = 0.f, lpb = 0.f;
            #pragma unroll
            for (int nt = 0; nt < 4; nt++) {
                const int cc = c0s + nt * 8 + ((lane & 3) << 1);
                float p0 = __expf(sacc[mt][nt][0] - M_REF);
                float p1 = __expf(sacc[mt][nt][1] - M_REF);
                float p2 = __expf(sacc[mt][nt][2] - M_REF);
                float p3 = __expf(sacc[mt][nt][3] - M_REF);
                if (is_new) {
                    const int j = C - CACHE + cc;
                    if (j     > m0 + ra) p0 = 0.f;
                    if (j + 1 > m0 + ra) p1 = 0.f;
                    if (j     > m0 + rb) p2 = 0.f;
                    if (j + 1 > m0 + rb) p3 = 0.f;
                }
                lpa += p0 + p1;
                lpb += p2 + p3;
                // accumulator fragment -> A fragment (rows ra block = reg0, rb block = reg1)
                split_pair(p0, p1, phi[mt][nt * 2 + 0], plo[mt][nt * 2 + 0]);
                split_pair(p2, p3, phi[mt][nt * 2 + 1], plo[mt][nt * 2 + 1]);
            }
            lpa += __shfl_xor_sync(0xffffffffu, lpa, 1);
            lpa += __shfl_xor_sync(0xffffffffu, lpa, 2);
            lpb += __shfl_xor_sync(0xffffffffu, lpb, 1);
            lpb += __shfl_xor_sync(0xffffffffu, lpb, 2);
            if ((lane & 3) == 0) {
                atomicAdd(&lrow[ra], lpa);
                atomicAdd(&lrow[rb], lpb);
            }
        }

        // ---- PV from registers: O_part += Ph*Vh + Ph*Vl + Pl*Vh over own k-slice ----
        pv_pass(phi, VH, c0s, lane, oacc);
        pv_pass(phi, VL, c0s, lane, oacc);
        pv_pass(plo, VH, c0s, lane, oacc);
        // no barrier here: next loop-top barrier covers buffer release
    }

    // ---- cross-k-slice reduction + finalize ----
    __syncthreads();                       // all PV + lrow atomics done
    float* scr = (float*)(smem + OFF_QHI); // reuse Q buffers: 128 x 132 f32 = 67.6KB
    const int SSTR = 132;
    if (wc == 1) {
        #pragma unroll
        for (int mt = 0; mt < 2; mt++) {
            const int ra = r0 + mt * 16 + (lane >> 2);
            const int rb = ra + 8;
            #pragma unroll
            for (int nb = 0; nb < 16; nb++) {
                const int dc = nb * 8 + ((lane & 3) << 1);
                *(float2*)(scr + ra * SSTR + dc) = make_float2(oacc[mt][nb][0], oacc[mt][nb][1]);
                *(float2*)(scr + rb * SSTR + dc) = make_float2(oacc[mt][nb][2], oacc[mt][nb][3]);
            }
        }
    }
    __syncthreads();
    if (wc == 0) {
        #pragma unroll
        for (int mt = 0; mt < 2; mt++) {
            const int ra = r0 + mt * 16 + (lane >> 2);
            const int rb = ra + 8;
            const float la = 1.0f / lrow[ra];
            const float lb = 1.0f / lrow[rb];
            #pragma unroll
            for (int nb = 0; nb < 16; nb++) {
                const int dc = nb * 8 + ((lane & 3) << 1);
                float2 oa = *(float2*)(scr + ra * SSTR + dc);
                float2 ob = *(float2*)(scr + rb * SSTR + dc);
                float* pa = out + ((long)h * BATCH + m0 + ra) * HEAD_DIM + dc;
                float* pb = out + ((long)h * BATCH + m0 + rb) * HEAD_DIM + dc;
                *(float2*)pa = make_float2((oacc[mt][nb][0] + oa.x) * la,
                                           (oacc[mt][nb][1] + oa.y) * la);
                *(float2*)pb = make_float2((oacc[mt][nb][2] + ob.x) * lb,
                                           (oacc[mt][nb][3] + ob.y) * lb);
            }
        }
    }
}

extern "C" void kernel_launch(void* const* d_in, const int* in_sizes, int n_in,
                              void* d_out, int out_size)
{
    const float* q      = (const float*)d_in[0];
    const float* keys   = (const float*)d_in[1];
    const float* ktc    = (const float*)d_in[2];
    const float* values = (const float*)d_in[3];
    const float* vc     = (const float*)d_in[4];
    // d_in[5] = attn_bias: analytic causal mask, not needed
    const float* kqs    = (const float*)d_in[6];

    float* out    = (float*)d_out;
    float* out_sk = out    + (long)NHEADS * BATCH * HEAD_DIM;
    float* out_sv = out_sk + (long)NKV    * BATCH * HEAD_DIM;

    cudaFuncSetAttribute(attn_hmma_kernel, cudaFuncAttributeMaxDynamicSharedMemorySize, SMEM_TOTAL);

    dim3 pgrid(CTX / 32, HEAD_DIM / 32, NKV);
    dim3 pblk(32, 8);
    prep_k<<<pgrid, pblk>>>(ktc, keys, kqs, out_sk);
    prep_v<<<pgrid, pblk>>>(vc, values, out_sv);

    dim3 grid(BATCH / BM, NHEADS);
    attn_hmma_kernel<<<grid, THREADS, SMEM_TOTAL>>>(q, out);
}

// round 13
// speedup vs baseline: 1.8896x; 1.2360x over previous
#include <cuda_runtime.h>
#include <cuda_bf16.h>
#include <cuda_fp16.h>
#include <cstdint>

#define NKV      8
#define GROUP    4
#define NHEADS   32
#define BATCH    512
#define HEAD_DIM 128
#define CACHE    2048
#define CTX      2560
#define NEG_INF  (-10000.0f)
#define THREADS  256
#define BM       128
#define BN       64

// ---- global pre-split K (bf16 hi/lo) + V (fp16) ----
__device__ __nv_bfloat16 KgHi[(long)NKV * CTX * HEAD_DIM];   // [kv][col][d]
__device__ __nv_bfloat16 KgLo[(long)NKV * CTX * HEAD_DIM];
__device__ __half        VgH [(long)NKV * HEAD_DIM * CTX];   // [kv][d][col]

// ---- smem layout ----
#define QK_STRIDE 272              // 128 k bf16 + 16B pad
#define V_STRIDE  144              // 64 k fp16 + 16B pad
#define OFF_M1   0                 // float m1[128]  (wc=1 partial max)
#define OFF_L1   512               // float l1[128]  (wc=1 partial sum)
#define OFF_QHI  1024
#define OFF_QLO  (OFF_QHI + 34816)
#define OFF_K0H  (OFF_QLO + 34816)
#define OFF_K0L  (OFF_K0H + 17408)
#define OFF_K1H  (OFF_K0L + 17408)
#define OFF_K1L  (OFF_K1H + 17408)
#define OFF_V0   (OFF_K1L + 17408)
#define OFF_V1   (OFF_V0  + 18432)
#define SMEM_TOTAL (OFF_V1 + 18432)   // 177152

__device__ __forceinline__ uint32_t smem_u32(const void* p) {
    uint32_t a;
    asm("{ .reg .u64 t; cvta.to.shared.u64 t, %1; cvt.u32.u64 %0, t; }" : "=r"(a) : "l"(p));
    return a;
}
__device__ __forceinline__ void ldsm4(uint32_t* r, uint32_t addr) {
    asm volatile("ldmatrix.sync.aligned.m8n8.x4.shared.b16 {%0,%1,%2,%3}, [%4];"
                 : "=r"(r[0]), "=r"(r[1]), "=r"(r[2]), "=r"(r[3]) : "r"(addr));
}
__device__ __forceinline__ void mma_bf16(float* c, const uint32_t* a, uint32_t b0, uint32_t b1) {
    asm volatile("mma.sync.aligned.m16n8k16.row.col.f32.bf16.bf16.f32 "
                 "{%0,%1,%2,%3}, {%4,%5,%6,%7}, {%8,%9}, {%0,%1,%2,%3};"
                 : "+f"(c[0]), "+f"(c[1]), "+f"(c[2]), "+f"(c[3])
                 : "r"(a[0]), "r"(a[1]), "r"(a[2]), "r"(a[3]), "r"(b0), "r"(b1));
}
__device__ __forceinline__ void mma_f16(float* c, const uint32_t* a, uint32_t b0, uint32_t b1) {
    asm volatile("mma.sync.aligned.m16n8k16.row.col.f32.f16.f16.f32 "
                 "{%0,%1,%2,%3}, {%4,%5,%6,%7}, {%8,%9}, {%0,%1,%2,%3};"
                 : "+f"(c[0]), "+f"(c[1]), "+f"(c[2]), "+f"(c[3])
                 : "r"(a[0]), "r"(a[1]), "r"(a[2]), "r"(a[3]), "r"(b0), "r"(b1));
}
__device__ __forceinline__ void cpa16(uint32_t s, const void* g) {
    asm volatile("{ .reg .u64 ga; cvta.to.global.u64 ga, %1; cp.async.ca.shared.global [%0], [ga], 16; }"
                 :: "r"(s), "l"(g) : "memory");
}
__device__ __forceinline__ void cp_commit() { asm volatile("cp.async.commit_group;" ::: "memory"); }
__device__ __forceinline__ void cp_wait0()  { asm volatile("cp.async.wait_group 0;"  ::: "memory"); }

__device__ __forceinline__ uint32_t bpack(float a, float b) {
    __nv_bfloat162 t = __floats2bfloat162_rn(a, b);
    return *reinterpret_cast<uint32_t*>(&t);
}
__device__ __forceinline__ void split_pair(float a, float b, uint32_t& hi, uint32_t& lo) {
    float ah = __bfloat162float(__float2bfloat16(a));
    float bh = __bfloat162float(__float2bfloat16(b));
    hi = bpack(ah, bh);
    lo = bpack(a - ah, b - bh);
}
__device__ __forceinline__ void split1(float v, __nv_bfloat16& hi, __nv_bfloat16& lo) {
    hi = __float2bfloat16(v);
    lo = __float2bfloat16(v - __bfloat162float(hi));
}
__device__ __forceinline__ uint32_t hpack(float a, float b) {
    __half2 t = __floats2half2_rn(a, b);
    return *reinterpret_cast<uint32_t*>(&t);
}

// QK pass (bf16): A rows r0..r0+31, B rows c0..c0+31, K=128. acc[2][4][4].
__device__ __forceinline__ void qk_pass(uint32_t Ab, uint32_t Bb, int r0, int c0,
                                        int lane, float acc[2][4][4]) {
    const int arow  = lane & 15;
    const int acolo = (lane >> 4) * 8;
    const int brow  = ((lane >> 4) << 3) + (lane & 7);
    const int bcolo = ((lane >> 3) & 1) * 8;
    #pragma unroll
    for (int kc = 0; kc < 8; kc++) {
        uint32_t a0[4], a1[4];
        ldsm4(a0, Ab + (uint32_t)((r0 + arow) * QK_STRIDE + (kc * 16 + acolo) * 2));
        ldsm4(a1, Ab + (uint32_t)((r0 + 16 + arow) * QK_STRIDE + (kc * 16 + acolo) * 2));
        #pragma unroll
        for (int np = 0; np < 2; np++) {
            uint32_t b[4];
            ldsm4(b, Bb + (uint32_t)((c0 + np * 16 + brow) * QK_STRIDE + (kc * 16 + bcolo) * 2));
            mma_bf16(acc[0][np * 2 + 0], a0, b[0], b[1]);
            mma_bf16(acc[0][np * 2 + 1], a0, b[2], b[3]);
            mma_bf16(acc[1][np * 2 + 0], a1, b[0], b[1]);
            mma_bf16(acc[1][np * 2 + 1], a1, b[2], b[3]);
        }
    }
}

// PV pass (fp16, single): A = P fragments in regs, B = V slice (k-cols kbase..+31).
__device__ __forceinline__ void pv_pass(const uint32_t pa[2][8], uint32_t Vb, int kbase,
                                        int lane, float acc[2][16][4]) {
    const int brow  = ((lane >> 4) << 3) + (lane & 7);
    const int bcolo = ((lane >> 3) & 1) * 8;
    #pragma unroll
    for (int kc = 0; kc < 2; kc++) {
        #pragma unroll
        for (int nb = 0; nb < 8; nb++) {
            uint32_t b[4];
            ldsm4(b, Vb + (uint32_t)((nb * 16 + brow) * V_STRIDE + (kbase + kc * 16 + bcolo) * 2));
            #pragma unroll
            for (int mt = 0; mt < 2; mt++) {
                mma_f16(acc[mt][nb * 2 + 0], &pa[mt][kc * 4], b[0], b[1]);
                mma_f16(acc[mt][nb * 2 + 1], &pa[mt][kc * 4], b[2], b[3]);
            }
        }
    }
}

// ============ pre-pass: split K (bf16 hi/lo) + scaled_keys ============
__global__ void prep_k(const float* __restrict__ ktc, const float* __restrict__ keys,
                       const float* __restrict__ kqs, float* __restrict__ out_sk)
{
    const int kv = blockIdx.z;
    const int c0 = blockIdx.x * 32;
    const int d0 = blockIdx.y * 32;
    const int tx = threadIdx.x, ty = threadIdx.y;
    __shared__ float tile[32][33];

    if (c0 < CACHE) {
        #pragma unroll
        for (int i = 0; i < 4; i++) {
            int d = d0 + ty + i * 8;
            tile[ty + i * 8][tx] = ktc[((long)kv * HEAD_DIM + d) * CACHE + c0 + tx];
        }
        __syncthreads();
        #pragma unroll
        for (int i = 0; i < 4; i++) {
            int c = c0 + ty + i * 8;
            int d = d0 + tx;
            float v = tile[tx][ty + i * 8];
            __nv_bfloat16 hi, lo;
            split1(v, hi, lo);
            long o = ((long)kv * CTX + c) * HEAD_DIM + d;
            KgHi[o] = hi; KgLo[o] = lo;
        }
    } else {
        const float s = kqs[0];
        const int b0 = c0 - CACHE;
        #pragma unroll
        for (int i = 0; i < 4; i++) {
            int b = b0 + ty + i * 8;
            int d = d0 + tx;
            float v = keys[((long)kv * BATCH + b) * HEAD_DIM + d] * s;
            out_sk[((long)kv * BATCH + b) * HEAD_DIM + d] = v;
            __nv_bfloat16 hi, lo;
            split1(v, hi, lo);
            long o = ((long)kv * CTX + CACHE + b) * HEAD_DIM + d;
            KgHi[o] = hi; KgLo[o] = lo;
        }
    }
}

// ============ pre-pass: V -> fp16 transpose + scaled_values ============
__global__ void prep_v(const float* __restrict__ vc, const float* __restrict__ values,
                       float* __restrict__ out_sv)
{
    const int kv = blockIdx.z;
    const int c0 = blockIdx.x * 32;
    const int d0 = blockIdx.y * 32;
    const int tx = threadIdx.x, ty = threadIdx.y;
    __shared__ float tile[32][33];

    if (c0 < CACHE) {
        #pragma unroll
        for (int i = 0; i < 4; i++) {
            int c = c0 + ty + i * 8;
            tile[ty + i * 8][tx] = vc[((long)kv * CACHE + c) * HEAD_DIM + d0 + tx];
        }
    } else {
        const int b0 = c0 - CACHE;
        #pragma unroll
        for (int i = 0; i < 4; i++) {
            int b = b0 + ty + i * 8;
            float v = fmaxf(values[((long)kv * BATCH + b) * HEAD_DIM + d0 + tx], NEG_INF);
            tile[ty + i * 8][tx] = v;
            out_sv[((long)kv * BATCH + b) * HEAD_DIM + d0 + tx] = v;
        }
    }
    __syncthreads();
    #pragma unroll
    for (int i = 0; i < 4; i++) {
        int d = d0 + ty + i * 8;
        int c = c0 + tx;
        float v = tile[tx][ty + i * 8];
        VgH[((long)kv * HEAD_DIM + d) * CTX + c] = __float2half_rn(v);
    }
}

// ============ main kernel ============
extern __shared__ __align__(16) char smem[];

__device__ __forceinline__ void stage_k(uint32_t sb, int buf, int kv, int C, int tid) {
    const __nv_bfloat16* gh = KgHi + ((long)kv * CTX + C) * HEAD_DIM;
    const __nv_bfloat16* gl = KgLo + ((long)kv * CTX + C) * HEAD_DIM;
    const uint32_t sh = sb + (buf ? OFF_K1H : OFF_K0H);
    const uint32_t sl = sb + (buf ? OFF_K1L : OFF_K0L);
    #pragma unroll
    for (int i = 0; i < 4; i++) {
        int idx = tid + i * THREADS;
        int r = idx >> 4, ch = idx & 15;
        cpa16(sh + r * QK_STRIDE + ch * 16, gh + r * HEAD_DIM + ch * 8);
        cpa16(sl + r * QK_STRIDE + ch * 16, gl + r * HEAD_DIM + ch * 8);
    }
}
__device__ __forceinline__ void stage_v(uint32_t sb, int buf, int kv, int C, int tid) {
    const __half* gh = VgH + (long)kv * HEAD_DIM * CTX + C;
    const uint32_t sh = sb + (buf ? OFF_V1 : OFF_V0);
    #pragma unroll
    for (int i = 0; i < 4; i++) {
        int idx = tid + i * THREADS;
        int r = idx >> 3, ch = idx & 7;
        cpa16(sh + r * V_STRIDE + ch * 16, gh + (long)r * CTX + ch * 8);
    }
}

__global__ void __launch_bounds__(THREADS, 1)
attn_hmma_kernel(const float* __restrict__ q,
                 float* __restrict__ out)
{
    const uint32_t sb = smem_u32(smem);
    const int tid  = threadIdx.x;
    const int w    = tid >> 5;
    const int lane = tid & 31;
    const int wr   = w & 3;            // 4 row groups of 32 rows
    const int wc   = w >> 2;           // 2 k-slice groups
    const int r0   = wr * 32;
    const int c0s  = wc * 32;          // this warp's score cols = its PV k-slice
    const int h    = blockIdx.y;
    const int kv   = h / GROUP;
    const int m0   = blockIdx.x * BM;

    const float* qbase = q + ((long)h * BATCH + m0) * HEAD_DIM;

    stage_k(sb, 0, kv, 0, tid);
    stage_v(sb, 0, kv, 0, tid);
    cp_commit();

    // ---- load Q (128x128) split into QHI/QLO ----
    for (int i = tid; i < 4096; i += THREADS) {
        int r  = i >> 5;
        int d4 = (i & 31) << 2;
        float4 v = *(const float4*)(qbase + (long)r * HEAD_DIM + d4);
        uint32_t h0, l0, h1, l1;
        split_pair(v.x, v.y, h0, l0);
        split_pair(v.z, v.w, h1, l1);
        uint32_t o = (uint32_t)(r * QK_STRIDE + d4 * 2);
        *(uint32_t*)(smem + OFF_QHI + o)     = h0;
        *(uint32_t*)(smem + OFF_QHI + o + 4) = h1;
        *(uint32_t*)(smem + OFF_QLO + o)     = l0;
        *(uint32_t*)(smem + OFF_QLO + o + 4) = l1;
    }

    float oacc[2][16][4];
    #pragma unroll
    for (int mt = 0; mt < 2; mt++)
        #pragma unroll
        for (int nb = 0; nb < 16; nb++)
            #pragma unroll
            for (int k = 0; k < 4; k++) oacc[mt][nb][k] = 0.0f;

    // per-warp online softmax state: rows ra(mt), rb(mt)
    float mrun[2][2] = {{-1e30f, -1e30f}, {-1e30f, -1e30f}};
    float lrun[2][2] = {{0.f, 0.f}, {0.f, 0.f}};

    const int ntiles = (CACHE + m0 + BM) / BN;

    for (int t = 0; t < ntiles; t++) {
        const int C = t * BN;
        const bool is_new = (C >= CACHE);
        const int buf = t & 1;
        const uint32_t KH = sb + (buf ? OFF_K1H : OFF_K0H);
        const uint32_t KL = sb + (buf ? OFF_K1L : OFF_K0L);
        const uint32_t VH = sb + (buf ? OFF_V1 : OFF_V0);

        cp_wait0();
        __syncthreads();

        if (t + 1 < ntiles) {
            stage_k(sb, buf ^ 1, kv, C + BN, tid);
            stage_v(sb, buf ^ 1, kv, C + BN, tid);
            cp_commit();
        }

        // ---- QK^T: S = Qh*Kh + Qh*Kl + Ql*Kh ----
        float sacc[2][4][4];
        #pragma unroll
        for (int mt = 0; mt < 2; mt++)
            #pragma unroll
            for (int nt = 0; nt < 4; nt++)
                #pragma unroll
                for (int k = 0; k < 4; k++) sacc[mt][nt][k] = 0.0f;

        qk_pass(sb + OFF_QHI, KH, r0, c0s, lane, sacc);
        qk_pass(sb + OFF_QHI, KL, r0, c0s, lane, sacc);
        qk_pass(sb + OFF_QLO, KH, r0, c0s, lane, sacc);

        // ---- causal mask on raw scores ----
        if (is_new) {
            #pragma unroll
            for (int mt = 0; mt < 2; mt++) {
                const int ra = r0 + mt * 16 + (lane >> 2);
                const int rb = ra + 8;
                #pragma unroll
                for (int nt = 0; nt < 4; nt++) {
                    const int j = C - CACHE + c0s + nt * 8 + ((lane & 3) << 1);
                    if (j     > m0 + ra) sacc[mt][nt][0] = -1e30f;
                    if (j + 1 > m0 + ra) sacc[mt][nt][1] = -1e30f;
                    if (j     > m0 + rb) sacc[mt][nt][2] = -1e30f;
                    if (j + 1 > m0 + rb) sacc[mt][nt][3] = -1e30f;
                }
            }
        }

        // ---- online softmax epilogue: p = exp(s - m_new) <= 1, fp16 P frags ----
        uint32_t phi[2][8];
        #pragma unroll
        for (int mt = 0; mt < 2; mt++) {
            // tile row maxes
            float ma = -1e30f, mb = -1e30f;
            #pragma unroll
            for (int nt = 0; nt < 4; nt++) {
                ma = fmaxf(ma, fmaxf(sacc[mt][nt][0], sacc[mt][nt][1]));
                mb = fmaxf(mb, fmaxf(sacc[mt][nt][2], sacc[mt][nt][3]));
            }
            ma = fmaxf(ma, __shfl_xor_sync(0xffffffffu, ma, 1));
            ma = fmaxf(ma, __shfl_xor_sync(0xffffffffu, ma, 2));
            mb = fmaxf(mb, __shfl_xor_sync(0xffffffffu, mb, 1));
            mb = fmaxf(mb, __shfl_xor_sync(0xffffffffu, mb, 2));

            const float mna = fmaxf(mrun[mt][0], ma);
            const float mnb = fmaxf(mrun[mt][1], mb);
            const float aa  = __expf(mrun[mt][0] - mna);
            const float ab  = __expf(mrun[mt][1] - mnb);
            mrun[mt][0] = mna;
            mrun[mt][1] = mnb;

            float lpa = 0.f, lpb = 0.f;
            #pragma unroll
            for (int nt = 0; nt < 4; nt++) {
                float p0 = __expf(sacc[mt][nt][0] - mna);
                float p1 = __expf(sacc[mt][nt][1] - mna);
                float p2 = __expf(sacc[mt][nt][2] - mnb);
                float p3 = __expf(sacc[mt][nt][3] - mnb);
                lpa += p0 + p1;
                lpb += p2 + p3;
                phi[mt][nt * 2 + 0] = hpack(p0, p1);
                phi[mt][nt * 2 + 1] = hpack(p2, p3);
            }
            lpa += __shfl_xor_sync(0xffffffffu, lpa, 1);
            lpa += __shfl_xor_sync(0xffffffffu, lpa, 2);
            lpb += __shfl_xor_sync(0xffffffffu, lpb, 1);
            lpb += __shfl_xor_sync(0xffffffffu, lpb, 2);
            lrun[mt][0] = lrun[mt][0] * aa + lpa;
            lrun[mt][1] = lrun[mt][1] * ab + lpb;

            // rescale this warp's O partial
            #pragma unroll
            for (int nb = 0; nb < 16; nb++) {
                oacc[mt][nb][0] *= aa;
                oacc[mt][nb][1] *= aa;
                oacc[mt][nb][2] *= ab;
                oacc[mt][nb][3] *= ab;
            }
        }

        // ---- PV (single fp16 pass): O_part += P*V over own k-slice ----
        pv_pass(phi, VH, c0s, lane, oacc);
    }

    // ---- cross-k-slice combine: O = (O0*e^{m0-M} + O1*e^{m1-M}) / (l0*e^{m0-M} + l1*e^{m1-M}) ----
    __syncthreads();
    float* m1s = (float*)(smem + OFF_M1);
    float* l1s = (float*)(smem + OFF_L1);
    float* scr = (float*)(smem + OFF_QHI);   // reuse Q buffers: 128 x 132 f32
    const int SSTR = 132;
    if (wc == 1) {
        #pragma unroll
        for (int mt = 0; mt < 2; mt++) {
            const int ra = r0 + mt * 16 + (lane >> 2);
            const int rb = ra + 8;
            if ((lane & 3) == 0) {
                m1s[ra] = mrun[mt][0]; l1s[ra] = lrun[mt][0];
                m1s[rb] = mrun[mt][1]; l1s[rb] = lrun[mt][1];
            }
            #pragma unroll
            for (int nb = 0; nb < 16; nb++) {
                const int dc = nb * 8 + ((lane & 3) << 1);
                *(float2*)(scr + ra * SSTR + dc) = make_float2(oacc[mt][nb][0], oacc[mt][nb][1]);
                *(float2*)(scr + rb * SSTR + dc) = make_float2(oacc[mt][nb][2], oacc[mt][nb][3]);
            }
        }
    }
    __syncthreads();
    if (wc == 0) {
        #pragma unroll
        for (int mt = 0; mt < 2; mt++) {
            const int ra = r0 + mt * 16 + (lane >> 2);
            const int rb = ra + 8;
            const float m1a = m1s[ra], m1b = m1s[rb];
            const float Ma = fmaxf(mrun[mt][0], m1a);
            const float Mb = fmaxf(mrun[mt][1], m1b);
            const float s0a = __expf(mrun[mt][0] - Ma), s1a = __expf(m1a - Ma);
            const float s0b = __expf(mrun[mt][1] - Mb), s1b = __expf(m1b - Mb);
            const float inva = 1.0f / (lrun[mt][0] * s0a + l1s[ra] * s1a);
            const float invb = 1.0f / (lrun[mt][1] * s0b + l1s[rb] * s1b);
            #pragma unroll
            for (int nb = 0; nb < 16; nb++) {
                const int dc = nb * 8 + ((lane & 3) << 1);
                float2 oa = *(float2*)(scr + ra * SSTR + dc);
                float2 ob = *(float2*)(scr + rb * SSTR + dc);
                float* pa = out + ((long)h * BATCH + m0 + ra) * HEAD_DIM + dc;
                float* pb = out + ((long)h * BATCH + m0 + rb) * HEAD_DIM + dc;
                *(float2*)pa = make_float2((oacc[mt][nb][0] * s0a + oa.x * s1a) * inva,
                                           (oacc[mt][nb][1] * s0a + oa.y * s1a) * inva);
                *(float2*)pb = make_float2((oacc[mt][nb][2] * s0b + ob.x * s1b) * invb,
                                           (oacc[mt][nb][3] * s0b + ob.y * s1b) * invb);
            }
        }
    }
}

extern "C" void kernel_launch(void* const* d_in, const int* in_sizes, int n_in,
                              void* d_out, int out_size)
{
    const float* q      = (const float*)d_in[0];
    const float* keys   = (const float*)d_in[1];
    const float* ktc    = (const float*)d_in[2];
    const float* values = (const float*)d_in[3];
    const float* vc     = (const float*)d_in[4];
    // d_in[5] = attn_bias: analytic causal mask, not needed
    const float* kqs    = (const float*)d_in[6];

    float* out    = (float*)d_out;
    float* out_sk = out    + (long)NHEADS * BATCH * HEAD_DIM;
    float* out_sv = out_sk + (long)NKV    * BATCH * HEAD_DIM;

    cudaFuncSetAttribute(attn_hmma_kernel, cudaFuncAttributeMaxDynamicSharedMemorySize, SMEM_TOTAL);

    dim3 pgrid(CTX / 32, HEAD_DIM / 32, NKV);
    dim3 pblk(32, 8);
    prep_k<<<pgrid, pblk>>>(ktc, keys, kqs, out_sk);
    prep_v<<<pgrid, pblk>>>(vc, values, out_sv);

    dim3 grid(BATCH / BM, NHEADS);
    attn_hmma_kernel<<<grid, THREADS, SMEM_TOTAL>>>(q, out);
}